// round 7
// baseline (speedup 1.0000x reference)
#include <cuda_runtime.h>
#include <cuda_bf16.h>

// LJ constants: EPSILON=1, SIGMA=1, CUTOFF=5
// SHIFT = 4*((1/5)^12 - (1/5)^6)
// per-edge half energy: h = 0.5*(4*(sr12 - sr6) - SHIFT) = 2*(sr12 - sr6) - SHIFT/2
static constexpr double SHIFT_D = 4.0 * (1.0 / 244140625.0 - 1.0 / 15625.0);
static constexpr float NEG_HALF_SHIFT = (float)(-0.5 * SHIFT_D);

__global__ void zero_out_kernel(float* __restrict__ out, int n) {
    int i = blockIdx.x * blockDim.x + threadIdx.x;
    if (i < n) out[i] = 0.0f;
}

__device__ __forceinline__ float half_edge_energy(float x, float y, float z) {
    float r2 = fmaf(x, x, fmaf(y, y, z * z));
    float inv = __fdividef(1.0f, r2);      // MUFU.RCP path
    float sr6 = inv * inv * inv;           // (sigma/r)^6, sigma=1
    float d = fmaf(sr6, sr6, -sr6);        // sr12 - sr6
    return fmaf(2.0f, d, NEG_HALF_SHIFT);  // 2*(sr12-sr6) - SHIFT/2
}

__global__ __launch_bounds__(256) void lj_scatter_kernel(
    const float* __restrict__ dist,   // [E,3] float32
    const int* __restrict__ ia,       // [E] int32 (JAX default config demotes int64)
    const int* __restrict__ ib,       // [E] int32
    float* __restrict__ out,          // [n_atoms]
    int n_edges)
{
    int g = blockIdx.x * blockDim.x + threadIdx.x;
    int base = g * 4;
    if (base >= n_edges) return;

    if (base + 3 < n_edges) {
        // 4 edges per thread. dist offset = 12*g floats = 48B -> 16B aligned.
        const float4* d4 = reinterpret_cast<const float4*>(dist + (size_t)base * 3);
        float4 p0 = d4[0];
        float4 p1 = d4[1];
        float4 p2 = d4[2];
        int4 a = *reinterpret_cast<const int4*>(ia + base);  // base % 4 == 0 -> 16B aligned
        int4 b = *reinterpret_cast<const int4*>(ib + base);

        float h0 = half_edge_energy(p0.x, p0.y, p0.z);
        float h1 = half_edge_energy(p0.w, p1.x, p1.y);
        float h2 = half_edge_energy(p1.z, p1.w, p2.x);
        float h3 = half_edge_energy(p2.y, p2.z, p2.w);

        // Return values discarded -> ptxas emits REDG (no-return atomics)
        atomicAdd(out + a.x, h0);
        atomicAdd(out + b.x, h0);
        atomicAdd(out + a.y, h1);
        atomicAdd(out + b.y, h1);
        atomicAdd(out + a.z, h2);
        atomicAdd(out + b.z, h2);
        atomicAdd(out + a.w, h3);
        atomicAdd(out + b.w, h3);
    } else {
        // Scalar tail
        for (int e = base; e < n_edges; ++e) {
            float x = dist[(size_t)e * 3 + 0];
            float y = dist[(size_t)e * 3 + 1];
            float z = dist[(size_t)e * 3 + 2];
            float h = half_edge_energy(x, y, z);
            atomicAdd(out + ia[e], h);
            atomicAdd(out + ib[e], h);
        }
    }
}

extern "C" void kernel_launch(void* const* d_in, const int* in_sizes, int n_in,
                              void* d_out, int out_size) {
    const float* dist = (const float*)d_in[0]; // [E,3] float32
    const int* ia = (const int*)d_in[1];       // [E] int32
    const int* ib = (const int*)d_in[2];       // [E] int32
    float* out = (float*)d_out;                // [n_atoms] float32

    int n_edges = in_sizes[1];   // element count of first_atom
    int n_atoms = out_size;

    // d_out is poisoned; zero it first (same stream -> ordered before scatter).
    {
        int tpb = 256;
        int blocks = (n_atoms + tpb - 1) / tpb;
        zero_out_kernel<<<blocks, tpb>>>(out, n_atoms);
    }

    {
        int tpb = 256;
        int groups = (n_edges + 3) / 4;
        int blocks = (groups + tpb - 1) / tpb;
        lj_scatter_kernel<<<blocks, tpb>>>(dist, ia, ib, out, n_edges);
    }
}